// round 11
// baseline (speedup 1.0000x reference)
#include <cuda_runtime.h>
#include <cstdint>

// SpikeFP32Embedding: out[t, :] = weight_pulse[token_ids[t], :]
// weight_pulse: [32768, 128, 32] fp32  -> 1024 float4 per row (16 KB)
// token_ids:    16384 int32
// out:          [16384, 4096] fp32  (256 MB)
//
// Final config at the practical roofline (~458 MB traffic = analytic floor,
// ~78% DRAM efficiency bound by read/write turnaround):
//   - one CTA per token, 256 threads x 4 LDG.128 front-batched
//   - reads:  ld.global.cg.v4 (L2-only; table rows have zero intra-SM reuse,
//             so L1 allocation is pure overhead)
//   - stores: default write-back STG.128 (best measured DRAM%: dirty lines
//             drain from L2 opportunistically, smoothing the R/W mix)

static constexpr int ROW_F4   = 1024;   // 4096 floats / 4
static constexpr int THREADS  = 256;
static constexpr int F4_PER_T = ROW_F4 / THREADS;  // 4

__device__ __forceinline__ float4 ldg_cg(const float4* addr) {
    float4 v;
    asm volatile("ld.global.cg.v4.f32 {%0, %1, %2, %3}, [%4];"
                 : "=f"(v.x), "=f"(v.y), "=f"(v.z), "=f"(v.w)
                 : "l"(addr));
    return v;
}

__global__ void __launch_bounds__(THREADS)
spike_embed_gather_final(const int* __restrict__ token_ids,
                         const float4* __restrict__ table,
                         float4* __restrict__ out)
{
    const int tok = blockIdx.x;
    const int row = __ldg(&token_ids[tok]);

    const float4* __restrict__ src = table + (size_t)row * ROW_F4;
    float4* __restrict__       dst = out   + (size_t)tok * ROW_F4;

    const int tid = threadIdx.x;
    float4 v[F4_PER_T];
#pragma unroll
    for (int i = 0; i < F4_PER_T; ++i)
        v[i] = ldg_cg(&src[tid + i * THREADS]);
#pragma unroll
    for (int i = 0; i < F4_PER_T; ++i)
        dst[tid + i * THREADS] = v[i];   // default write-back STG.128
}

extern "C" void kernel_launch(void* const* d_in, const int* in_sizes, int n_in,
                              void* d_out, int out_size)
{
    // Resolve inputs by element count:
    //   token_ids:    16384
    //   weight_pulse: 134217728
    const int* token_ids = nullptr;
    const float4* table  = nullptr;
    for (int i = 0; i < n_in; ++i) {
        if (in_sizes[i] == 16384)          token_ids = (const int*)d_in[i];
        else if (in_sizes[i] == 134217728) table     = (const float4*)d_in[i];
    }

    const int n_tokens = 16384;
    spike_embed_gather_final<<<n_tokens, THREADS>>>(token_ids, table, (float4*)d_out);
}